// round 14
// baseline (speedup 1.0000x reference)
#include <cuda_runtime.h>
#include <cuda_bf16.h>

#define FULLMASK 0xffffffffu

static const int B = 64;
static const int S = 512;
static const int T = 16;      // tags
static const int K = 300;     // embed dim
static const int ROWS = B * S;           // 32768
static const int C = 16;      // chunks per sequence
static const int L = 32;      // steps per chunk
static const int KS_LEN = 100;           // k per split (3 splits)

// scratch (no allocations allowed -> device globals)
__device__ float g_part[3][ROWS * T];     // probs partials per k-split
__device__ float g_Mexp[B * C * T * T];   // exp(M - rowmax), row-normalized
__device__ float g_carry[B * C * T];      // per-row log carry
__device__ float g_usum[B * C];           // unary partial per chunk
__device__ float g_bsum[B * C];           // binary partial per chunk
__device__ int   g_len[B];                // sequence lengths

// ============================================================
// Kernel 1: partial probs. Block (rb, ks): rows rb*64..+63, k ks*100..+99.
// 256 threads, TM=1 x TN=4. No swizzle:
//   E pitch = 25 float4 (odd) -> (row + c) mod 8 naturally conflict-free.
//   W kept native [k][j] -> (4k + cg) mod 8 4-distinct broadcast.
// ============================================================
static const int PR_ROWS = 64;

__global__ __launch_bounds__(256)
void probs_kernel(const int* __restrict__ text,
                  const float* __restrict__ embed,
                  const float* __restrict__ W,
                  const float* __restrict__ bvec) {
    __shared__ __align__(16) float4 Esh4[PR_ROWS * 25];  // 25.6 KB, odd pitch
    __shared__ __align__(16) float4 Wsh4[KS_LEN * 4];    // 6.4 KB, native layout
    __shared__ int tok_sh[PR_ROWS];

    const int tid  = threadIdx.x;
    const int rb   = blockIdx.x;
    const int ks   = blockIdx.y;
    const int row0 = rb * PR_ROWS;
    const int k0   = ks * KS_LEN;

    if (tid < PR_ROWS) tok_sh[tid] = text[row0 + tid];

    // W slice: contiguous 400 float4 copy (no transpose)
    const float4* Wg = (const float4*)(W + (size_t)k0 * T);
    #pragma unroll
    for (int i = tid; i < KS_LEN * 4; i += 256) Wsh4[i] = Wg[i];
    __syncthreads();   // tok_sh ready

    // E staging: 64 rows x 25 float4, coalesced (c = idx&31, 25 active)
    #pragma unroll
    for (int it = 0; it < 8; ++it) {
        int idx = tid + it * 256;
        int row = idx >> 5;
        int c   = idx & 31;
        if (c < 25) {
            const float4* src = (const float4*)(embed + (size_t)tok_sh[row] * K + k0);
            Esh4[row * 25 + c] = src[c];
        }
    }
    __syncthreads();

    const int row = tid >> 2;       // 0..63
    const int cg  = tid & 3;        // col group
    const int j0  = cg * 4;
    const float4* Erow = Esh4 + row * 25;

    float4 acc = make_float4(0.f, 0.f, 0.f, 0.f);

    #pragma unroll
    for (int k4 = 0; k4 < 25; ++k4) {
        float4 e  = Erow[k4];
        float4 w0 = Wsh4[(k4 * 4 + 0) * 4 + cg];
        float4 w1 = Wsh4[(k4 * 4 + 1) * 4 + cg];
        float4 w2 = Wsh4[(k4 * 4 + 2) * 4 + cg];
        float4 w3 = Wsh4[(k4 * 4 + 3) * 4 + cg];
        acc.x = fmaf(e.x, w0.x, acc.x);
        acc.y = fmaf(e.x, w0.y, acc.y);
        acc.z = fmaf(e.x, w0.z, acc.z);
        acc.w = fmaf(e.x, w0.w, acc.w);
        acc.x = fmaf(e.y, w1.x, acc.x);
        acc.y = fmaf(e.y, w1.y, acc.y);
        acc.z = fmaf(e.y, w1.z, acc.z);
        acc.w = fmaf(e.y, w1.w, acc.w);
        acc.x = fmaf(e.z, w2.x, acc.x);
        acc.y = fmaf(e.z, w2.y, acc.y);
        acc.z = fmaf(e.z, w2.z, acc.z);
        acc.w = fmaf(e.z, w2.w, acc.w);
        acc.x = fmaf(e.w, w3.x, acc.x);
        acc.y = fmaf(e.w, w3.y, acc.y);
        acc.z = fmaf(e.w, w3.z, acc.z);
        acc.w = fmaf(e.w, w3.w, acc.w);
    }

    if (ks == 0) {
        float4 bj = *(const float4*)(bvec + j0);
        acc.x += bj.x; acc.y += bj.y; acc.z += bj.z; acc.w += bj.w;
    }
    *(float4*)(g_part[ks] + (size_t)(row0 + row) * T + j0) = acc;
}

// ============================================================
// Kernel 2: per-(batch, chunk) transfer matrix, linear domain.
// 256 threads = 16 rows x 16 lanes. Scan via smem double-buffered
// row-broadcast (no shfl gather). Also folds k-split partials into
// probs output, and computes unary/binary/len partials (warp 0).
// ============================================================
__global__ __launch_bounds__(256, 4)
void chunk_kernel(const int* __restrict__ text,
                  const int* __restrict__ tags,
                  const float* __restrict__ trans,
                  float* __restrict__ probs_out) {
    const int c   = blockIdx.x;
    const int b   = blockIdx.y;
    const int tid = threadIdx.x;
    const int j   = tid & 15;
    const int row = tid >> 4;

    __shared__ float tsh[256];
    __shared__ float esh[L * 16];
    __shared__ float psh2[2][256];
    __shared__ int   lred[8];

    const int s0     = 1 + c * L;
    const int send   = min(s0 + L, S);
    const int nsteps = send - s0;
    const int nload  = nsteps * 16;
    const int base0  = (b * S + s0) * 16;

    tsh[tid] = trans[tid];

    // sequence length
    const int* txt = text + b * S;
    int cnt = (txt[tid] != 0 ? 1 : 0) + (txt[tid + 256] != 0 ? 1 : 0);
    #pragma unroll
    for (int off = 16; off; off >>= 1) cnt += __shfl_xor_sync(FULLMASK, cnt, off);
    if ((tid & 31) == 0) lred[tid >> 5] = cnt;

    // fold partials -> probs_out, and stage exp(emit)
    const float* p0 = g_part[0] + base0;
    const float* p1 = g_part[1] + base0;
    const float* p2 = g_part[2] + base0;
    float* op = probs_out + base0;
    #pragma unroll
    for (int it = 0; it < 2; ++it) {
        int i = tid + it * 256;
        if (i < nload) {
            float sv = p0[i] + p1[i] + p2[i];
            op[i] = sv;
            esh[i] = __expf(sv);
        } else {
            esh[i] = 1.0f;
        }
    }
    if (c == 0 && tid < 16) {   // row s=0 (alpha0 source)
        int bi = b * S * 16 + tid;
        probs_out[bi] = g_part[0][bi] + g_part[1][bi] + g_part[2][bi];
    }
    __syncthreads();

    int len = 0;
    #pragma unroll
    for (int wgi = 0; wgi < 8; ++wgi) len += lred[wgi];
    const int lenc = min(len, S);

    // warp 0: unary/binary partials for this chunk's s-range
    if (tid < 32) {
        const int* tg = tags + b * S;
        int q = tid;
        int s = s0 + q;
        float uu = 0.f, bb = 0.f;
        if (q < nsteps && s < lenc) {
            int t = tg[s];
            uu = op[q * 16 + t];
            bb = tsh[tg[s - 1] * 16 + t];
        }
        if (c == 0 && tid == 0 && lenc > 0)
            uu += probs_out[b * S * 16 + tg[0]];   // s=0 unary
        #pragma unroll
        for (int off = 16; off; off >>= 1) {
            uu += __shfl_xor_sync(FULLMASK, uu, off);
            bb += __shfl_xor_sync(FULLMASK, bb, off);
        }
        if (tid == 0) {
            g_usum[b * C + c] = uu;
            g_bsum[b * C + c] = bb;
            if (c == 0) g_len[b] = lenc;
        }
    }

    // scan: transfer matrix rows in linear domain
    float E[16];
    #pragma unroll
    for (int k = 0; k < 16; ++k) E[k] = __expf(tsh[k * 16 + j]);

    float p     = (row == j) ? 1.0f : 0.0f;
    float carry = 0.0f;
    int   cur   = 0;
    psh2[0][row * 16 + j] = p;

    for (int qb = 0; qb < L; qb += 8) {
        #pragma unroll
        for (int q2 = 0; q2 < 8; ++q2) {
            const int q = qb + q2;
            const int s = s0 + q;
            __syncwarp();
            const float4* prow = (const float4*)(psh2[cur] + row * 16);
            float4 a0 = prow[0], a1 = prow[1], a2 = prow[2], a3 = prow[3];
            float t0 = a0.x * E[0];
            float t1 = a0.y * E[1];
            float t2 = a0.z * E[2];
            float t3 = a0.w * E[3];
            t0 = fmaf(a1.x, E[4],  t0);
            t1 = fmaf(a1.y, E[5],  t1);
            t2 = fmaf(a1.z, E[6],  t2);
            t3 = fmaf(a1.w, E[7],  t3);
            t0 = fmaf(a2.x, E[8],  t0);
            t1 = fmaf(a2.y, E[9],  t1);
            t2 = fmaf(a2.z, E[10], t2);
            t3 = fmaf(a2.w, E[11], t3);
            t0 = fmaf(a3.x, E[12], t0);
            t1 = fmaf(a3.y, E[13], t1);
            t2 = fmaf(a3.z, E[14], t2);
            t3 = fmaf(a3.w, E[15], t3);
            float pn = ((t0 + t1) + (t2 + t3)) * esh[q * 16 + j];
            p = (s < lenc) ? pn : p;
            cur ^= 1;
            psh2[cur][row * 16 + j] = p;
        }
        // renormalize row by its max; accumulate log in carry
        float mx = p;
        mx = fmaxf(mx, __shfl_xor_sync(FULLMASK, mx, 1, 16));
        mx = fmaxf(mx, __shfl_xor_sync(FULLMASK, mx, 2, 16));
        mx = fmaxf(mx, __shfl_xor_sync(FULLMASK, mx, 4, 16));
        mx = fmaxf(mx, __shfl_xor_sync(FULLMASK, mx, 8, 16));
        carry += __logf(mx);
        p *= (1.0f / mx);
        psh2[cur][row * 16 + j] = p;
    }

    g_Mexp[((b * C + c) * 16 + row) * 16 + j] = p;
    if (j == 0) g_carry[(b * C + c) * 16 + row] = carry;
}

// ============================================================
// Kernel 3: per-batch — sum partials, fold alpha0 through C chunk
// matrices, final logsumexp -> log-likelihood.
// ============================================================
__global__ __launch_bounds__(32, 1)
void combine_kernel(const float* __restrict__ probs,
                    float* __restrict__ out_tail) {
    const int b    = blockIdx.x;
    const int lane = threadIdx.x;
    const int j    = lane & 15;

    __shared__ float Msh[C * 256];   // [c][i][j], straight copy
    __shared__ float csh[C * 16];
    __shared__ float psh[16];

    const float* Mb = g_Mexp + (size_t)b * C * 256;
    for (int i4 = lane; i4 < C * 64; i4 += 32)
        ((float4*)Msh)[i4] = ((const float4*)Mb)[i4];
    for (int i = lane; i < C * 16; i += 32) csh[i] = g_carry[b * C * 16 + i];
    __syncwarp();

    // unary + binary partial sums
    float u = 0.f, bsc = 0.f;
    if (lane < 16) { u = g_usum[b * C + lane]; bsc = g_bsum[b * C + lane]; }
    #pragma unroll
    for (int off = 16; off; off >>= 1) {
        u   += __shfl_xor_sync(FULLMASK, u, off);
        bsc += __shfl_xor_sync(FULLMASK, bsc, off);
    }
    const int len = g_len[b];

    // fold alpha0 through chunk matrices
    float v = probs[(size_t)b * S * T + j];
    #pragma unroll
    for (int cc = 0; cc < C; ++cc) {
        float w = v + csh[cc * 16 + j];
        float m = w;
        m = fmaxf(m, __shfl_xor_sync(FULLMASK, m, 1, 16));
        m = fmaxf(m, __shfl_xor_sync(FULLMASK, m, 2, 16));
        m = fmaxf(m, __shfl_xor_sync(FULLMASK, m, 4, 16));
        m = fmaxf(m, __shfl_xor_sync(FULLMASK, m, 8, 16));
        float pi = __expf(w - m);
        if (lane < 16) psh[lane] = pi;
        __syncwarp();
        float acc = 0.f;
        #pragma unroll
        for (int i = 0; i < 16; ++i)
            acc = fmaf(psh[i], Msh[cc * 256 + i * 16 + j], acc);
        v = __logf(acc) + m;
        __syncwarp();
    }

    // log_norm
    float m = v;
    m = fmaxf(m, __shfl_xor_sync(FULLMASK, m, 1, 16));
    m = fmaxf(m, __shfl_xor_sync(FULLMASK, m, 2, 16));
    m = fmaxf(m, __shfl_xor_sync(FULLMASK, m, 4, 16));
    m = fmaxf(m, __shfl_xor_sync(FULLMASK, m, 8, 16));
    float ex = __expf(v - m);
    ex += __shfl_xor_sync(FULLMASK, ex, 1, 16);
    ex += __shfl_xor_sync(FULLMASK, ex, 2, 16);
    ex += __shfl_xor_sync(FULLMASK, ex, 4, 16);
    ex += __shfl_xor_sync(FULLMASK, ex, 8, 16);
    float logn = m + __logf(ex);

    if (lane == 0) {
        out_tail[b]     = (float)len;
        out_tail[B + b] = u + bsc - logn;
    }
}

// ============================================================
extern "C" void kernel_launch(void* const* d_in, const int* in_sizes, int n_in,
                              void* d_out, int out_size) {
    const int*   text  = (const int*)d_in[0];
    const int*   tags  = (const int*)d_in[1];
    const float* embed = (const float*)d_in[2];
    const float* W     = (const float*)d_in[3];
    const float* bvec  = (const float*)d_in[4];
    const float* trans = (const float*)d_in[5];
    float* out = (float*)d_out;

    probs_kernel<<<dim3(ROWS / PR_ROWS, 3), 256>>>(text, embed, W, bvec);
    chunk_kernel<<<dim3(C, B), 256>>>(text, tags, trans, out);
    combine_kernel<<<B, 32>>>(out, out + (size_t)ROWS * T);
}